// round 1
// baseline (speedup 1.0000x reference)
#include <cuda_runtime.h>

#define BB 512
#define TT 2048
#define KK 32
#define NW 342   // ceil((TT-1)/6) words of packed backpointers (6 x 5-bit per u32)

__global__ void __launch_bounds__(32, 4) crf_viterbi_kernel(
    const float* __restrict__ pot,     // [B, T, K]
    const float* __restrict__ trans,   // [K, K]
    float* __restrict__ out)           // [B, T, K] one-hot
{
    __shared__ unsigned int bpW[NW][KK];                 // 43776 B
    __shared__ __align__(16) float stateSm[2][KK];       // 256 B
    __shared__ unsigned char tagSm[TT];                  // 2048 B

    const int lane = threadIdx.x;
    const int b    = blockIdx.x;
    const float* p = pot + (size_t)b * TT * KK + lane;

    // transitions column `lane`: tj[i] = trans[i][lane]  (coalesced per i)
    float tj[KK];
#pragma unroll
    for (int i = 0; i < KK; i++) tj[i] = __ldg(trans + i * KK + lane);

    // state at t=0
    float s = p[0];

    // software-pipelined potential prefetch, distance 6 (>= DRAM latency)
    float pf[6];
#pragma unroll
    for (int k = 0; k < 6; k++) pf[k] = p[(size_t)(1 + k) * KK];

    for (int w = 0; w < NW; w++) {
        unsigned int acc = 0;
#pragma unroll
        for (int k = 0; k < 6; k++) {
            const int t = 1 + 6 * w + k;
            if (t < TT) {
                const int buf = k & 1;                    // uniform across lanes
                stateSm[buf][lane] = s;
                __syncwarp();
                const float4* sp = (const float4*)stateSm[buf];
                float sv[KK];
#pragma unroll
                for (int q = 0; q < 8; q++) {
                    float4 r = sp[q];
                    sv[4*q+0] = r.x; sv[4*q+1] = r.y;
                    sv[4*q+2] = r.z; sv[4*q+3] = r.w;
                }
                // scores for this lane's target state j=lane
                float v[KK];
#pragma unroll
                for (int i = 0; i < KK; i++) v[i] = sv[i] + tj[i];

                // argmax tree, first-index tie-break (take upper only on strict >)
                float m1[16]; int i1[16];
#pragma unroll
                for (int i = 0; i < 16; i++) {
                    bool g = v[2*i+1] > v[2*i];
                    m1[i] = g ? v[2*i+1] : v[2*i];
                    i1[i] = g ? 2*i+1 : 2*i;
                }
                float m2[8]; int i2[8];
#pragma unroll
                for (int i = 0; i < 8; i++) {
                    bool g = m1[2*i+1] > m1[2*i];
                    m2[i] = g ? m1[2*i+1] : m1[2*i];
                    i2[i] = g ? i1[2*i+1] : i1[2*i];
                }
                float m3[4]; int i3[4];
#pragma unroll
                for (int i = 0; i < 4; i++) {
                    bool g = m2[2*i+1] > m2[2*i];
                    m3[i] = g ? m2[2*i+1] : m2[2*i];
                    i3[i] = g ? i2[2*i+1] : i2[2*i];
                }
                float m4[2]; int i4[2];
#pragma unroll
                for (int i = 0; i < 2; i++) {
                    bool g = m3[2*i+1] > m3[2*i];
                    m4[i] = g ? m3[2*i+1] : m3[2*i];
                    i4[i] = g ? i3[2*i+1] : i3[2*i];
                }
                bool g5 = m4[1] > m4[0];
                float m  = g5 ? m4[1] : m4[0];
                int  bp  = g5 ? i4[1] : i4[0];

                const float pcur = pf[k];
                int tn = t + 6; if (tn > TT - 1) tn = TT - 1;
                pf[k] = p[(size_t)tn * KK];

                s = m + pcur;
                acc |= (unsigned int)bp << (5 * k);
            }
        }
        bpW[w][lane] = acc;
    }

    // final tag = argmax over lanes of s (first index on ties)
    stateSm[0][lane] = s;
    __syncwarp();
    float best = stateSm[0][0];
    int tag = 0;
#pragma unroll
    for (int i = 1; i < KK; i++) {
        float x = stateSm[0][i];
        if (x > best) { best = x; tag = i; }
    }

    // backtrack (serial chain through smem-packed backpointers)
    if (lane == 0) {
        tagSm[TT - 1] = (unsigned char)tag;
        int tg = tag;
        for (int t = TT - 1; t >= 1; t--) {
            const int idx = t - 1;
            const int w   = idx / 6;
            const int pos = idx - w * 6;
            const unsigned int word = bpW[w][tg];
            tg = (int)((word >> (5 * pos)) & 31u);
            tagSm[t - 1] = (unsigned char)tg;
        }
    }
    __syncwarp();

    // one-hot output, 128-bit stores: 4 rows per iteration, 8 lanes per row
    float* ob = out + (size_t)b * TT * KK;
    const int q  = lane & 7;        // which float4 within the row
    const int dt = lane >> 3;       // which of the 4 rows
    for (int t0 = 0; t0 < TT; t0 += 4) {
        const int t  = t0 + dt;
        const int tg = (int)tagSm[t];
        float4 val;
        val.x = (tg == 4*q + 0) ? 1.0f : 0.0f;
        val.y = (tg == 4*q + 1) ? 1.0f : 0.0f;
        val.z = (tg == 4*q + 2) ? 1.0f : 0.0f;
        val.w = (tg == 4*q + 3) ? 1.0f : 0.0f;
        *(float4*)(ob + (size_t)t * KK + 4 * q) = val;
    }
}

extern "C" void kernel_launch(void* const* d_in, const int* in_sizes, int n_in,
                              void* d_out, int out_size)
{
    const float* pot   = (const float*)d_in[0];   // inputs [512,2048,32]
    const float* trans = (const float*)d_in[1];   // transitions [32,32]
    float* out = (float*)d_out;
    crf_viterbi_kernel<<<BB, KK>>>(pot, trans, out);
}